// round 7
// baseline (speedup 1.0000x reference)
#include <cuda_runtime.h>
#include <cuda_bf16.h>
#include <cstdint>
#include <math.h>

#define BATCH  4
#define SEQ    4096
#define DMODEL 1024
#define DH     64
#define NCHUNK 8
#define ATTN_BLOCKS 576      // 4 batches * 144 = sum over 32 q-tiles of (qt>>2)+1

// ---------------------------------------------------------------------------
// Scratch (device globals, no allocation)
// ---------------------------------------------------------------------------
__device__ float g_qh[BATCH * SEQ * DH];
__device__ float g_kh[BATCH * SEQ * DH];
__device__ float g_vh[BATCH * SEQ * DH];
__device__ float g_po[NCHUNK][BATCH * SEQ * DH];
__device__ float g_pm[NCHUNK][BATCH * SEQ];
__device__ float g_pl[NCHUNK][BATCH * SEQ];
__device__ uint32_t g_wh[3 * 64 * 512];   // W bf16 hi, bf16x2 words [which][n][k/2]
__device__ uint32_t g_wl[3 * 64 * 512];

// ---------------------------------------------------------------------------
__device__ __forceinline__ void mma16816(float c[4], const uint32_t a[4],
                                         uint32_t b0, uint32_t b1) {
    asm volatile(
        "mma.sync.aligned.m16n8k16.row.col.f32.bf16.bf16.f32 "
        "{%0,%1,%2,%3}, {%4,%5,%6,%7}, {%8,%9}, {%0,%1,%2,%3};"
        : "+f"(c[0]), "+f"(c[1]), "+f"(c[2]), "+f"(c[3])
        : "r"(a[0]), "r"(a[1]), "r"(a[2]), "r"(a[3]), "r"(b0), "r"(b1));
}
__device__ __forceinline__ uint32_t cvt_hi(float2 f) {
    __nv_bfloat162 h = __floats2bfloat162_rn(f.x, f.y);
    return *(uint32_t*)&h;
}
__device__ __forceinline__ uint32_t cvt_lo(float2 f, uint32_t hi) {
    __nv_bfloat162 h = *(__nv_bfloat162*)&hi;
    __nv_bfloat162 l = __floats2bfloat162_rn(f.x - __low2float(h),
                                             f.y - __high2float(h));
    return *(uint32_t*)&l;
}

// FMA-pipe exp (no MUFU), for x <= ~0
__device__ __forceinline__ float fast_exp(float x) {
    x = fmaxf(x, -87.0f);
    const float L2E = 1.4426950408889634f;
    float ys = fmaf(x, L2E, 12582912.0f);
    int   n  = __float_as_int(ys) - 0x4B400000;
    float nf = ys - 12582912.0f;
    float f  = fmaf(x, L2E, -nf);
    float p  = 1.3298820e-3f;
    p = fmaf(p, f, 9.6181291e-3f);
    p = fmaf(p, f, 5.5504109e-2f);
    p = fmaf(p, f, 2.4022649e-1f);
    p = fmaf(p, f, 6.9314718e-1f);
    p = fmaf(p, f, 1.0f);
    return __int_as_float((n + 127) << 23) * p;
}

// ---------------------------------------------------------------------------
__global__ __launch_bounds__(256)
void wconv_kernel(const float* __restrict__ wq, const float* __restrict__ wk,
                  const float* __restrict__ wv)
{
    const int t = blockIdx.x * 256 + threadIdx.x;
    const int which = t >> 15;
    const int p = t & 32767;
    const float* w = (which == 0) ? wq : (which == 1) ? wk : wv;
    float2 f = *(const float2*)(w + 2 * p);
    uint32_t h = cvt_hi(f);
    g_wh[t] = h;
    g_wl[t] = cvt_lo(f, h);
}

// ---------------------------------------------------------------------------
// Projection: smem-staged HMMA, interleaved hi/lo (word pair per (r,k2)).
// Block = 64 rows x 64 n, 4 warps, K chunked by 64.
// ---------------------------------------------------------------------------
__global__ __launch_bounds__(128)
void proj_mma_kernel(const float* __restrict__ qin, const float* __restrict__ kin,
                     const float* __restrict__ vin,
                     const float* __restrict__ bq, const float* __restrict__ bk,
                     const float* __restrict__ bv)
{
    __shared__ uint32_t Xs[64 * 36 * 2];
    __shared__ uint32_t Ws[64 * 36 * 2];

    const int which = blockIdx.y;
    const float* __restrict__ x    = (which == 0) ? qin : (which == 1) ? kin : vin;
    const float* __restrict__ bias = (which == 0) ? bq  : (which == 1) ? bk  : bv;
    float* __restrict__ out        = (which == 0) ? g_qh : (which == 1) ? g_kh : g_vh;
    const uint32_t* __restrict__ wh = g_wh + which * 32768;
    const uint32_t* __restrict__ wl = g_wl + which * 32768;

    const int tid  = threadIdx.x;
    const int warp = tid >> 5;
    const int lane = tid & 31;
    const int gid  = lane >> 2;
    const int tig  = lane & 3;
    const int row0 = blockIdx.x * 64;

    float acc[8][4] = {};

    for (int kb = 0; kb < 16; kb++) {
        __syncthreads();
        #pragma unroll
        for (int it = 0; it < 8; it++) {
            const int f = it * 128 + tid;
            const int r = f >> 4;
            const int c4 = (f & 15) << 2;
            float4 v = *(const float4*)(x + (size_t)(row0 + r) * DMODEL + kb * 64 + c4);
            uint32_t h0 = cvt_hi(make_float2(v.x, v.y));
            uint32_t h1 = cvt_hi(make_float2(v.z, v.w));
            uint32_t l0 = cvt_lo(make_float2(v.x, v.y), h0);
            uint32_t l1 = cvt_lo(make_float2(v.z, v.w), h1);
            *(uint4*)&Xs[(r * 36 + (c4 >> 1)) * 2] = make_uint4(h0, l0, h1, l1);
        }
        #pragma unroll
        for (int it = 0; it < 16; it++) {
            const int f = it * 128 + tid;
            const int n = f >> 5;
            const int k2 = f & 31;
            *(uint2*)&Ws[(n * 36 + k2) * 2] =
                make_uint2(wh[n * 512 + kb * 32 + k2], wl[n * 512 + kb * 32 + k2]);
        }
        __syncthreads();

        #pragma unroll
        for (int ks = 0; ks < 4; ks++) {
            const int d2 = (ks << 3) + tig;
            const int ra = (warp << 4) + gid;
            uint32_t ah[4], al[4];
            uint2 a0 = *(uint2*)&Xs[(ra * 36 + d2) * 2];
            uint2 a1 = *(uint2*)&Xs[((ra + 8) * 36 + d2) * 2];
            uint2 a2 = *(uint2*)&Xs[(ra * 36 + d2 + 4) * 2];
            uint2 a3 = *(uint2*)&Xs[((ra + 8) * 36 + d2 + 4) * 2];
            ah[0] = a0.x; al[0] = a0.y; ah[1] = a1.x; al[1] = a1.y;
            ah[2] = a2.x; al[2] = a2.y; ah[3] = a3.x; al[3] = a3.y;
            #pragma unroll
            for (int nt = 0; nt < 8; nt++) {
                const int nr = (nt << 3) + gid;
                uint2 b0 = *(uint2*)&Ws[(nr * 36 + d2) * 2];
                uint2 b1 = *(uint2*)&Ws[(nr * 36 + d2 + 4) * 2];
                mma16816(acc[nt], ah, b0.x, b1.x);
                mma16816(acc[nt], ah, b0.y, b1.y);
                mma16816(acc[nt], al, b0.x, b1.x);
            }
        }
    }

    const int row = row0 + (warp << 4) + gid;
    #pragma unroll
    for (int nt = 0; nt < 8; nt++) {
        const int col = (nt << 3) + (tig << 1);
        const float b0 = bias[col], b1 = bias[col + 1];
        *(float2*)(out + (size_t)row * DH + col) =
            make_float2(acc[nt][0] + b0, acc[nt][1] + b1);
        *(float2*)(out + (size_t)(row + 8) * DH + col) =
            make_float2(acc[nt][2] + b0, acc[nt][3] + b1);
    }
}

// ---------------------------------------------------------------------------
// Flash attention, mma.sync, split-KV. Block = 256 thr (8 warps), q-tile 128,
// chunk = 8 k-tiles (512 keys). Interleaved hi/lo smem.
// ---------------------------------------------------------------------------
__global__ __launch_bounds__(256, 2)
void attn_kernel()
{
    __shared__ uint32_t Ks[64 * 36 * 2];    // [key][d2] pairs
    __shared__ uint32_t Vs[64 * 36 * 2];    // [d][k2] pairs (transposed)

    const int tid  = threadIdx.x;
    const int warp = tid >> 5;
    const int lane = tid & 31;
    const int gid  = lane >> 2;
    const int tig  = lane & 3;

    const int bgid = (ATTN_BLOCKS - 1) - blockIdx.x;
    const int bb   = bgid / 144;
    const int r    = bgid - bb * 144;
    int m = 0;
    #pragma unroll
    for (int t = 1; t < 8; t++)
        if (2 * t * (t + 1) <= r) m = t;
    const int rr = r - 2 * m * (m + 1);
    const int qt = 4 * m + rr / (m + 1);
    const int ch = rr - (rr / (m + 1)) * (m + 1);

    const int q0  = qt * 128;
    const int kt0 = ch * 8;
    const int kt1 = min(kt0 + 7, 2 * qt + 1);

    const float* __restrict__ qh = g_qh + (size_t)bb * SEQ * DH;
    const float* __restrict__ kh = g_kh + (size_t)bb * SEQ * DH;
    const float* __restrict__ vh = g_vh + (size_t)bb * SEQ * DH;

    // Q fragments (hi/lo) in registers
    uint32_t qfh[4][4], qfl[4][4];
    const int rowA = q0 + (warp << 4) + gid;
    const int rowB = rowA + 8;
    {
        #pragma unroll
        for (int ks = 0; ks < 4; ks++) {
            const float* p0 = qh + (size_t)rowA * DH + (ks << 4) + (tig << 1);
            float2 f0 = *(const float2*)(p0);
            float2 f1 = *(const float2*)(p0 + 8 * DH);
            float2 f2 = *(const float2*)(p0 + 8);
            float2 f3 = *(const float2*)(p0 + 8 * DH + 8);
            qfh[ks][0] = cvt_hi(f0); qfl[ks][0] = cvt_lo(f0, qfh[ks][0]);
            qfh[ks][1] = cvt_hi(f1); qfl[ks][1] = cvt_lo(f1, qfh[ks][1]);
            qfh[ks][2] = cvt_hi(f2); qfl[ks][2] = cvt_lo(f2, qfh[ks][2]);
            qfh[ks][3] = cvt_hi(f3); qfl[ks][3] = cvt_lo(f3, qfh[ks][3]);
        }
    }

    float o[8][4] = {};
    float mA = -3.0e38f, mB = -3.0e38f, lA = 0.0f, lB = 0.0f;

    for (int kt = kt0; kt <= kt1; kt++) {
        const int k0 = kt * 64;
        __syncthreads();
        // stage K: 64 keys x 64 d, hi/lo interleaved, STS.128
        #pragma unroll
        for (int it = 0; it < 4; it++) {
            const int f = it * 256 + tid;
            const int rk = f >> 4;
            const int c4 = (f & 15) << 2;
            float4 v = *(const float4*)(kh + (size_t)(k0 + rk) * DH + c4);
            uint32_t h0 = cvt_hi(make_float2(v.x, v.y));
            uint32_t h1 = cvt_hi(make_float2(v.z, v.w));
            uint32_t l0 = cvt_lo(make_float2(v.x, v.y), h0);
            uint32_t l1 = cvt_lo(make_float2(v.z, v.w), h1);
            *(uint4*)&Ks[(rk * 36 + (c4 >> 1)) * 2] = make_uint4(h0, l0, h1, l1);
        }
        // stage V transposed: word (d, k2) = (V[2k2][d], V[2k2+1][d]); lane = k2
        #pragma unroll
        for (int it = 0; it < 2; it++) {
            const int f = it * 256 + tid;
            const int k2 = f & 31;
            const int dg = f >> 5;            // 0..15
            float4 v0 = *(const float4*)(vh + (size_t)(k0 + 2 * k2) * DH + 4 * dg);
            float4 v1 = *(const float4*)(vh + (size_t)(k0 + 2 * k2 + 1) * DH + 4 * dg);
            float p0[4] = {v0.x, v0.y, v0.z, v0.w};
            float p1[4] = {v1.x, v1.y, v1.z, v1.w};
            #pragma unroll
            for (int j = 0; j < 4; j++) {
                float2 pr = make_float2(p0[j], p1[j]);
                uint32_t h = cvt_hi(pr);
                uint32_t l = cvt_lo(pr, h);
                *(uint2*)&Vs[((4 * dg + j) * 36 + k2) * 2] = make_uint2(h, l);
            }
        }
        __syncthreads();

        // S = Q K^T
        float s[8][4] = {};
        #pragma unroll
        for (int ks = 0; ks < 4; ks++) {
            const int d2 = (ks << 3) + tig;
            #pragma unroll
            for (int nt = 0; nt < 8; nt++) {
                const int kr = (nt << 3) + gid;
                uint2 b0 = *(uint2*)&Ks[(kr * 36 + d2) * 2];
                uint2 b1 = *(uint2*)&Ks[(kr * 36 + d2 + 4) * 2];
                mma16816(s[nt], qfh[ks], b0.x, b1.x);
                mma16816(s[nt], qfh[ks], b0.y, b1.y);
                mma16816(s[nt], qfl[ks], b0.x, b1.x);
            }
        }

        // scale + causal mask (only tiles with k0 >= q0 can mask)
        if (kt >= 2 * qt) {
            #pragma unroll
            for (int nt = 0; nt < 8; nt++) {
                const int cb = k0 + (nt << 3) + (tig << 1);
                s[nt][0] = (cb     > rowA) ? -1.0e30f : s[nt][0] * 0.125f;
                s[nt][1] = (cb + 1 > rowA) ? -1.0e30f : s[nt][1] * 0.125f;
                s[nt][2] = (cb     > rowB) ? -1.0e30f : s[nt][2] * 0.125f;
                s[nt][3] = (cb + 1 > rowB) ? -1.0e30f : s[nt][3] * 0.125f;
            }
        } else {
            #pragma unroll
            for (int nt = 0; nt < 8; nt++) {
                s[nt][0] *= 0.125f; s[nt][1] *= 0.125f;
                s[nt][2] *= 0.125f; s[nt][3] *= 0.125f;
            }
        }

        // online softmax
        float mxA = -3.0e38f, mxB = -3.0e38f;
        #pragma unroll
        for (int nt = 0; nt < 8; nt++) {
            mxA = fmaxf(mxA, fmaxf(s[nt][0], s[nt][1]));
            mxB = fmaxf(mxB, fmaxf(s[nt][2], s[nt][3]));
        }
        mxA = fmaxf(mxA, __shfl_xor_sync(0xffffffffu, mxA, 1));
        mxA = fmaxf(mxA, __shfl_xor_sync(0xffffffffu, mxA, 2));
        mxB = fmaxf(mxB, __shfl_xor_sync(0xffffffffu, mxB, 1));
        mxB = fmaxf(mxB, __shfl_xor_sync(0xffffffffu, mxB, 2));
        const float mnA = fmaxf(mA, mxA), mnB = fmaxf(mB, mxB);
        const float aA = fast_exp(mA - mnA), aB = fast_exp(mB - mnB);
        mA = mnA; mB = mnB;
        float sumA = 0.0f, sumB = 0.0f;
        #pragma unroll
        for (int nt = 0; nt < 8; nt++) {
            s[nt][0] = fast_exp(s[nt][0] - mnA);
            s[nt][1] = fast_exp(s[nt][1] - mnA);
            s[nt][2] = fast_exp(s[nt][2] - mnB);
            s[nt][3] = fast_exp(s[nt][3] - mnB);
            sumA += s[nt][0] + s[nt][1];
            sumB += s[nt][2] + s[nt][3];
        }
        lA = lA * aA + sumA;
        lB = lB * aB + sumB;
        #pragma unroll
        for (int nt = 0; nt < 8; nt++) {
            o[nt][0] *= aA; o[nt][1] *= aA;
            o[nt][2] *= aB; o[nt][3] *= aB;
        }

        // O += P V
        #pragma unroll
        for (int kk = 0; kk < 4; kk++) {
            uint32_t ph[4], pl[4];
            float2 p0 = make_float2(s[2 * kk][0],     s[2 * kk][1]);
            float2 p1 = make_float2(s[2 * kk][2],     s[2 * kk][3]);
            float2 p2 = make_float2(s[2 * kk + 1][0], s[2 * kk + 1][1]);
            float2 p3 = make_float2(s[2 * kk + 1][2], s[2 * kk + 1][3]);
            ph[0] = cvt_hi(p0); pl[0] = cvt_lo(p0, ph[0]);
            ph[1] = cvt_hi(p1); pl[1] = cvt_lo(p1, ph[1]);
            ph[2] = cvt_hi(p2); pl[2] = cvt_lo(p2, ph[2]);
            ph[3] = cvt_hi(p3); pl[3] = cvt_lo(p3, ph[3]);
            const int k2 = (kk << 3) + tig;
            #pragma unroll
            for (int nt = 0; nt < 8; nt++) {
                const int dr = (nt << 3) + gid;
                uint2 b0 = *(uint2*)&Vs[(dr * 36 + k2) * 2];
                uint2 b1 = *(uint2*)&Vs[(dr * 36 + k2 + 4) * 2];
                mma16816(o[nt], ph, b0.x, b1.x);
                mma16816(o[nt], ph, b0.y, b1.y);
                mma16816(o[nt], pl, b0.x, b1.x);
            }
        }
    }

    // finalize partials
    lA += __shfl_xor_sync(0xffffffffu, lA, 1);
    lA += __shfl_xor_sync(0xffffffffu, lA, 2);
    lB += __shfl_xor_sync(0xffffffffu, lB, 1);
    lB += __shfl_xor_sync(0xffffffffu, lB, 2);

    const int growA = bb * SEQ + rowA;
    const int growB = bb * SEQ + rowB;
    #pragma unroll
    for (int nt = 0; nt < 8; nt++) {
        const int col = (nt << 3) + (tig << 1);
        *(float2*)&g_po[ch][(size_t)growA * DH + col] = make_float2(o[nt][0], o[nt][1]);
        *(float2*)&g_po[ch][(size_t)growB * DH + col] = make_float2(o[nt][2], o[nt][3]);
    }
    if (tig == 0) {
        g_pm[ch][growA] = mA; g_pl[ch][growA] = lA;
        g_pm[ch][growB] = mB; g_pl[ch][growB] = lB;
    }
}

// ---------------------------------------------------------------------------
__global__ __launch_bounds__(256)
void merge_kernel(float* __restrict__ out)
{
    const int t = blockIdx.x * 256 + threadIdx.x;
    const int row = t >> 4;
    const int cg  = (t & 15) << 2;
    const int q   = row & (SEQ - 1);
    const int nc  = (q >> 9) + 1;            // 512-key chunks

    float mstar = -3.0e38f;
    #pragma unroll 4
    for (int c = 0; c < nc; c++)
        mstar = fmaxf(mstar, g_pm[c][row]);

    float L = 0.0f;
    float4 acc = make_float4(0.f, 0.f, 0.f, 0.f);
    #pragma unroll 4
    for (int c = 0; c < nc; c++) {
        const float wgt = __expf(g_pm[c][row] - mstar);
        L += wgt * g_pl[c][row];
        float4 ov = *(const float4*)&g_po[c][(size_t)row * DH + cg];
        acc.x += wgt * ov.x; acc.y += wgt * ov.y;
        acc.z += wgt * ov.z; acc.w += wgt * ov.w;
    }
    const float inv = 1.0f / L;
    *(float4*)(out + (size_t)row * DH + cg) =
        make_float4(acc.x * inv, acc.y * inv, acc.z * inv, acc.w * inv);
}

// ---------------------------------------------------------------------------
extern "C" void kernel_launch(void* const* d_in, const int* in_sizes, int n_in,
                              void* d_out, int out_size)
{
    (void)in_sizes; (void)n_in; (void)out_size;
    const float* q  = (const float*)d_in[0];
    const float* k  = (const float*)d_in[1];
    const float* v  = (const float*)d_in[2];
    const float* wq = (const float*)d_in[3];
    const float* bq = (const float*)d_in[4];
    const float* wk = (const float*)d_in[5];
    const float* bk = (const float*)d_in[6];
    const float* wv = (const float*)d_in[7];
    const float* bv = (const float*)d_in[8];
    float* out = (float*)d_out;

    wconv_kernel<<<384, 256>>>(wq, wk, wv);
    dim3 pgrid(BATCH * SEQ / 64, 3);   // (256, 3)
    proj_mma_kernel<<<pgrid, 128>>>(q, k, v, bq, bk, bv);
    attn_kernel<<<ATTN_BLOCKS, 256>>>();
    merge_kernel<<<BATCH * SEQ * 16 / 256, 256>>>(out);
}